// round 2
// baseline (speedup 1.0000x reference)
#include <cuda_runtime.h>

// Problem constants (fixed-shape problem)
#define NE   640000     // edges
#define NV   160000     // nodes
#define NG   5000       // graphs
#define HID  256        // hidden width

// ---------------- device scratch (no allocations allowed) ----------------
__device__ float g_h0[(size_t)NE * HID];  // 655 MB
__device__ float g_hA[(size_t)NE * HID];  // 655 MB
__device__ float g_hB[(size_t)NE * HID];  // 655 MB
__device__ float g_ns[(size_t)NV * HID];  // 164 MB  (node segment sums)
__device__ int   g_src32[NE];
__device__ int   g_dst32[NE];
__device__ int   g_rev32[NE];
__device__ int   g_batch32[NV];
__device__ int   g_is64;

// ---------------- packed fp32x2 helpers ----------------
__device__ __forceinline__ unsigned long long pk2(float x, float y) {
    unsigned long long r;
    asm("mov.b64 %0, {%1, %2};" : "=l"(r) : "r"(__float_as_uint(x)), "r"(__float_as_uint(y)));
    return r;
}
__device__ __forceinline__ unsigned long long pk1(float x) {
    unsigned long long r;
    asm("mov.b64 %0, {%1, %1};" : "=l"(r) : "r"(__float_as_uint(x)));
    return r;
}
__device__ __forceinline__ void fma2(unsigned long long& d, unsigned long long a, unsigned long long b) {
    asm("fma.rn.f32x2 %0, %1, %2, %0;" : "+l"(d) : "l"(a), "l"(b));
}
__device__ __forceinline__ void unpack2(unsigned long long v, float& lo, float& hi) {
    unsigned int a, b;
    asm("mov.b64 {%0, %1}, %2;" : "=r"(a), "=r"(b) : "l"(v));
    lo = __uint_as_float(a);
    hi = __uint_as_float(b);
}
__device__ __forceinline__ void red4(float* p, float4 v) {
    asm volatile("red.global.add.v4.f32 [%0], {%1, %2, %3, %4};"
                 :: "l"(p), "f"(v.x), "f"(v.y), "f"(v.z), "f"(v.w) : "memory");
}
__device__ __forceinline__ float4 relu4(float a, float b, float c, float d) {
    return make_float4(fmaxf(a, 0.f), fmaxf(b, 0.f), fmaxf(c, 0.f), fmaxf(d, 0.f));
}

// ---------------- index dtype detection + normalization ----------------
// edge_index values are uniform random in [0, 160000). If the buffer is int64,
// the odd 32-bit words (high halves) are all zero. If it's int32, odd words are
// random indices (all-zero probability ~ (1/160000)^64 ~ 0).
__global__ void detect_kernel(const unsigned int* __restrict__ ei_words) {
    if (threadIdx.x == 0 && blockIdx.x == 0) {
        int allz = 1;
        #pragma unroll 1
        for (int i = 1; i < 128; i += 2) allz &= (ei_words[i] == 0u);
        g_is64 = allz;
    }
}

__global__ void convert_kernel(const void* __restrict__ ei,
                               const void* __restrict__ rev,
                               const void* __restrict__ batch) {
    int i = blockIdx.x * 256 + threadIdx.x;   // grid covers NE
    const bool is64 = (g_is64 != 0);
    if (i < NE) {
        if (is64) {
            g_src32[i] = (int)((const long long*)ei)[i];
            g_dst32[i] = (int)((const long long*)ei)[NE + i];
            g_rev32[i] = (int)((const long long*)rev)[i];
        } else {
            g_src32[i] = ((const int*)ei)[i];
            g_dst32[i] = ((const int*)ei)[NE + i];
            g_rev32[i] = ((const int*)rev)[i];
        }
    }
    if (i < NV) {
        g_batch32[i] = is64 ? (int)((const long long*)batch)[i]
                            : ((const int*)batch)[i];
    }
}

// ---------------- utility kernels ----------------
__global__ void zero_ns_kernel() {
    size_t i = (size_t)blockIdx.x * blockDim.x + threadIdx.x;   // NV*HID/4 threads
    ((float4*)g_ns)[i] = make_float4(0.f, 0.f, 0.f, 0.f);
}

__global__ void zero_buf_kernel(float4* p) {
    size_t i = (size_t)blockIdx.x * blockDim.x + threadIdx.x;
    p[i] = make_float4(0.f, 0.f, 0.f, 0.f);
}

// segment_sum: scatter h (hsel: 1=g_hA, 2=g_hB) into g_ns by dst.
__global__ void scatter_kernel(int hsel) {
    const float* h = (hsel == 1) ? g_hA : g_hB;
    long long gid = (long long)blockIdx.x * 256 + threadIdx.x;
    int e = (int)(gid >> 6);
    int c = (int)(gid & 63) << 2;
    int d = g_dst32[e];
    float4 v = *(const float4*)&h[(size_t)e * HID + c];
    red4(&g_ns[(size_t)d * HID + c], v);
}

// ---------------- fused gathered SGEMM ----------------
// MODE 0: A[e,k] = k<128 ? x[src[e],k] : ea[e,k-128]   (K=192), C=relu(A@W1) -> g_h0 AND g_hA
// MODE 1: A[e,k] = g_ns[src[e],k] - hin[rev[e],k]       (K=256), C=relu(g_h0 + A@W2) -> hout
// MODE 2: A[n,k] = k<128 ? x[n,k] : g_ns[n,k-128]       (K=384), C=relu(A@W3+b3), red-add -> out[batch[n]]
// Tile: BM=64, BN=256 (full), BK=16, 256 threads, 8x8 per thread, f32x2 accumulators.
template <int MODE>
__global__ void __launch_bounds__(256, 2) gemm_kernel(
    const float* __restrict__ x, const float* __restrict__ ea,
    const float* __restrict__ W, const float* __restrict__ b3,
    float* out_global, int hin_sel, int hout_sel)
{
    constexpr int K = (MODE == 0) ? 192 : (MODE == 1 ? 256 : 384);

    __shared__ __align__(16) float As[16][64];    // A tile, transposed [k][m]
    __shared__ __align__(16) float Bs[16][256];   // B tile [k][n]
    __shared__ int sSrc[64];
    __shared__ int sRev[64];

    const int tid  = threadIdx.x;
    const int tx   = tid & 31;      // 32 col-groups of 8
    const int ty   = tid >> 5;      // 8 row-groups of 8
    const int row0 = blockIdx.x * 64;
    const int arow = tid >> 2;      // 0..63 : A row within tile
    const int akg  = tid & 3;       // 0..3  : which float4 along k

    const float* hin  = (hin_sel == 1) ? g_hA : g_hB;
    float*       hout = (hout_sel == 1) ? g_hA : g_hB;

    if (MODE == 0) {
        if (tid < 64) sSrc[tid] = g_src32[row0 + tid];
    } else if (MODE == 1) {
        if (tid < 64) { sSrc[tid] = g_src32[row0 + tid]; sRev[tid] = g_rev32[row0 + tid]; }
    }
    __syncthreads();

    unsigned long long acc[8][4];
    #pragma unroll
    for (int i = 0; i < 8; i++)
        #pragma unroll
        for (int j = 0; j < 4; j++) acc[i][j] = 0ULL;

    for (int k0 = 0; k0 < K; k0 += 16) {
        // ---- global loads into registers ----
        const int gk = k0 + akg * 4;
        float4 av;
        if (MODE == 0) {
            if (gk < 128) av = *(const float4*)&x[(size_t)sSrc[arow] * 128 + gk];
            else          av = *(const float4*)&ea[(size_t)(row0 + arow) * 64 + (gk - 128)];
        } else if (MODE == 1) {
            float4 p = *(const float4*)&g_ns[(size_t)sSrc[arow] * HID + gk];
            float4 q = *(const float4*)&hin [(size_t)sRev[arow] * HID + gk];
            av = make_float4(p.x - q.x, p.y - q.y, p.z - q.z, p.w - q.w);
        } else {
            if (gk < 128) av = *(const float4*)&x[(size_t)(row0 + arow) * 128 + gk];
            else          av = *(const float4*)&g_ns[(size_t)(row0 + arow) * HID + (gk - 128)];
        }
        float4 bv[4];
        #pragma unroll
        for (int i = 0; i < 4; i++) {
            int idx = tid + i * 256;
            int kr = idx >> 6, nc = idx & 63;
            bv[i] = *(const float4*)&W[(size_t)(k0 + kr) * 256 + nc * 4];
        }

        __syncthreads();   // previous chunk's compute done before overwrite

        // ---- store tiles to smem ----
        As[akg * 4 + 0][arow] = av.x;
        As[akg * 4 + 1][arow] = av.y;
        As[akg * 4 + 2][arow] = av.z;
        As[akg * 4 + 3][arow] = av.w;
        #pragma unroll
        for (int i = 0; i < 4; i++) {
            int idx = tid + i * 256;
            int kr = idx >> 6, nc = idx & 63;
            *(float4*)&Bs[kr][nc * 4] = bv[i];
        }
        __syncthreads();

        // ---- compute 16 k-steps, 8x8 outputs via packed f32x2 FMA ----
        #pragma unroll
        for (int kk = 0; kk < 16; kk++) {
            float4 a0 = *(const float4*)&As[kk][ty * 8];
            float4 a1 = *(const float4*)&As[kk][ty * 8 + 4];
            float4 b0 = *(const float4*)&Bs[kk][tx * 8];
            float4 b1 = *(const float4*)&Bs[kk][tx * 8 + 4];
            unsigned long long bp0 = pk2(b0.x, b0.y);
            unsigned long long bp1 = pk2(b0.z, b0.w);
            unsigned long long bp2 = pk2(b1.x, b1.y);
            unsigned long long bp3 = pk2(b1.z, b1.w);
            float a[8] = {a0.x, a0.y, a0.z, a0.w, a1.x, a1.y, a1.z, a1.w};
            #pragma unroll
            for (int i = 0; i < 8; i++) {
                unsigned long long ap = pk1(a[i]);
                fma2(acc[i][0], ap, bp0);
                fma2(acc[i][1], ap, bp1);
                fma2(acc[i][2], ap, bp2);
                fma2(acc[i][3], ap, bp3);
            }
        }
    }

    // ---- epilogue ----
    float4 bb0, bb1;
    if (MODE == 2) {
        bb0 = *(const float4*)&b3[tx * 8];
        bb1 = *(const float4*)&b3[tx * 8 + 4];
    }

    #pragma unroll
    for (int i = 0; i < 8; i++) {
        const int r = row0 + ty * 8 + i;
        float c[8];
        #pragma unroll
        for (int j = 0; j < 4; j++) unpack2(acc[i][j], c[2 * j], c[2 * j + 1]);

        const size_t off = (size_t)r * HID + tx * 8;
        if (MODE == 0) {
            float4 lo = relu4(c[0], c[1], c[2], c[3]);
            float4 hi = relu4(c[4], c[5], c[6], c[7]);
            *(float4*)&g_h0[off]     = lo;  *(float4*)&g_h0[off + 4] = hi;
            *(float4*)&g_hA[off]     = lo;  *(float4*)&g_hA[off + 4] = hi;
        } else if (MODE == 1) {
            float4 h0lo = *(const float4*)&g_h0[off];
            float4 h0hi = *(const float4*)&g_h0[off + 4];
            float4 lo = relu4(c[0] + h0lo.x, c[1] + h0lo.y, c[2] + h0lo.z, c[3] + h0lo.w);
            float4 hi = relu4(c[4] + h0hi.x, c[5] + h0hi.y, c[6] + h0hi.z, c[7] + h0hi.w);
            *(float4*)&hout[off]     = lo;  *(float4*)&hout[off + 4] = hi;
        } else {
            float4 lo = relu4(c[0] + bb0.x, c[1] + bb0.y, c[2] + bb0.z, c[3] + bb0.w);
            float4 hi = relu4(c[4] + bb1.x, c[5] + bb1.y, c[6] + bb1.z, c[7] + bb1.w);
            int g = g_batch32[r];
            red4(&out_global[(size_t)g * HID + tx * 8], lo);
            red4(&out_global[(size_t)g * HID + tx * 8 + 4], hi);
        }
    }
}

// ---------------- launcher ----------------
extern "C" void kernel_launch(void* const* d_in, const int* in_sizes, int n_in,
                              void* d_out, int out_size)
{
    // Bind inputs by element count (all sizes are distinct)
    const float *x = nullptr, *ea = nullptr, *W1 = nullptr, *W2 = nullptr, *W3 = nullptr, *b3 = nullptr;
    const void *ei = nullptr, *rev = nullptr, *batch = nullptr;
    for (int i = 0; i < n_in; i++) {
        switch (in_sizes[i]) {
            case 20480000: x     = (const float*)d_in[i]; break; // [160000,128]
            case  1280000: ei    = d_in[i];                break; // [2,640000]
            case   640000: rev   = d_in[i];                break; // [640000]
            case 40960000: ea    = (const float*)d_in[i]; break; // [640000,64]
            case   160000: batch = d_in[i];                break; // [160000]
            case    49152: W1    = (const float*)d_in[i]; break; // [192,256]
            case    65536: W2    = (const float*)d_in[i]; break; // [256,256]
            case    98304: W3    = (const float*)d_in[i]; break; // [384,256]
            case      256: b3    = (const float*)d_in[i]; break; // [256]
            default: break; // num_nodes scalar
        }
    }
    float* out = (float*)d_out;

    const int GEMM_E_GRID = NE / 64;   // 10000
    const int GEMM_N_GRID = NV / 64;   // 2500
    const int NS_ZERO_GRID = (NV * HID / 4) / 256;      // 40000
    const int SCATTER_GRID = NE * 64 / 256;             // 160000
    const int OUT_ZERO_GRID = (NG * HID / 4) / 256;     // 1250
    const int CONV_GRID = NE / 256;                     // 2500

    // index dtype detection + int32 normalization
    detect_kernel<<<1, 32>>>((const unsigned int*)ei);
    convert_kernel<<<CONV_GRID, 256>>>(ei, rev, batch);

    // h0 = relu(concat(x[src], ea) @ W1); h = h0
    gemm_kernel<0><<<GEMM_E_GRID, 256>>>(x, ea, W1, b3, nullptr, 0, 0);

    // iteration 1: h (hA) -> hB
    zero_ns_kernel<<<NS_ZERO_GRID, 256>>>();
    scatter_kernel<<<SCATTER_GRID, 256>>>(1);
    gemm_kernel<1><<<GEMM_E_GRID, 256>>>(x, ea, W2, b3, nullptr, 1, 2);

    // iteration 2: h (hB) -> hA
    zero_ns_kernel<<<NS_ZERO_GRID, 256>>>();
    scatter_kernel<<<SCATTER_GRID, 256>>>(2);
    gemm_kernel<1><<<GEMM_E_GRID, 256>>>(x, ea, W2, b3, nullptr, 2, 1);

    // final: v_msg = segment_sum(hA, dst); out = segment_sum(relu(concat(x,v_msg)@W3+b3), batch)
    zero_ns_kernel<<<NS_ZERO_GRID, 256>>>();
    scatter_kernel<<<SCATTER_GRID, 256>>>(1);
    zero_buf_kernel<<<OUT_ZERO_GRID, 256>>>((float4*)out);
    gemm_kernel<2><<<GEMM_N_GRID, 256>>>(x, ea, W3, b3, out, 0, 0);
}

// round 4
// speedup vs baseline: 1.1304x; 1.1304x over previous
#include <cuda_runtime.h>
#include <cuda_bf16.h>
#include <cstdint>

#define NE 640000
#define NV 160000
#define NG 5000

// ---------------- device scratch ----------------
__device__ float g_h0[(size_t)NE * 256];
__device__ float g_hB[(size_t)NE * 256];
__device__ float g_nsA[(size_t)NV * 256];
__device__ float g_nsB[(size_t)NV * 256];
__device__ int   g_src32[NE];
__device__ int   g_dst32[NE];
__device__ int   g_rev32[NE];
__device__ int   g_batch32[NV];
__device__ int   g_is64;
// Weights transposed to [n][k] (n=256 rows, k contiguous), bf16 hi/lo split.
#define BOFF_W1 0
#define BOFF_W2 (256 * 192)
#define BOFF_W3 (256 * 448)
__device__ __nv_bfloat16 g_bhi[256 * 832];
__device__ __nv_bfloat16 g_blo[256 * 832];

// ---------------- smem layout ----------------
// [0,256)   sA idx; [256,512) sB idx; [512,768) sC idx; pad to 1024
// tiles: per buffer: Ahi(64x40 bf16=5120) Alo(5120) Bhi(256x40 bf16=20480) Blo(20480)
#define SM_TILES 1024
#define T_AHI 0
#define T_ALO 5120
#define T_BHI 10240
#define T_BLO 30720
#define BUFSZ 51200
#define SMEM_TOTAL (1024 + 2 * BUFSZ)   // 103424
// epilogue C stage: 64 x 264 f32 = 67584 bytes at SM_TILES (reuses tile area)

// ---------------- helpers ----------------
__device__ __forceinline__ void mma_bf16(float* d, const uint32_t* a, const uint32_t* b) {
    asm volatile("mma.sync.aligned.m16n8k16.row.col.f32.bf16.bf16.f32 "
        "{%0,%1,%2,%3}, {%4,%5,%6,%7}, {%8,%9}, {%0,%1,%2,%3};"
        : "+f"(d[0]), "+f"(d[1]), "+f"(d[2]), "+f"(d[3])
        : "r"(a[0]), "r"(a[1]), "r"(a[2]), "r"(a[3]), "r"(b[0]), "r"(b[1]));
}
__device__ __forceinline__ void split2(float a, float b, uint32_t& hi, uint32_t& lo) {
    __nv_bfloat162 h = __floats2bfloat162_rn(a, b);
    float ra = a - __bfloat162float(h.x);
    float rb = b - __bfloat162float(h.y);
    __nv_bfloat162 l = __floats2bfloat162_rn(ra, rb);
    hi = *reinterpret_cast<uint32_t*>(&h);
    lo = *reinterpret_cast<uint32_t*>(&l);
}
__device__ __forceinline__ void red4(float* p, float4 v) {
    asm volatile("red.global.add.v4.f32 [%0], {%1, %2, %3, %4};"
                 :: "l"(p), "f"(v.x), "f"(v.y), "f"(v.z), "f"(v.w) : "memory");
}
__device__ __forceinline__ float4 relu4f(float4 v) {
    return make_float4(fmaxf(v.x, 0.f), fmaxf(v.y, 0.f), fmaxf(v.z, 0.f), fmaxf(v.w, 0.f));
}

// ---------------- index dtype detection + normalization ----------------
__global__ void detect_kernel(const unsigned int* __restrict__ ei_words) {
    if (threadIdx.x == 0 && blockIdx.x == 0) {
        int allz = 1;
        #pragma unroll 1
        for (int i = 1; i < 128; i += 2) allz &= (ei_words[i] == 0u);
        g_is64 = allz;
    }
}
__global__ void convert_kernel(const void* __restrict__ ei, const void* __restrict__ rev,
                               const void* __restrict__ batch) {
    int i = blockIdx.x * 256 + threadIdx.x;
    const bool is64 = (g_is64 != 0);
    if (i < NE) {
        if (is64) {
            g_src32[i] = (int)((const long long*)ei)[i];
            g_dst32[i] = (int)((const long long*)ei)[NE + i];
            g_rev32[i] = (int)((const long long*)rev)[i];
        } else {
            g_src32[i] = ((const int*)ei)[i];
            g_dst32[i] = ((const int*)ei)[NE + i];
            g_rev32[i] = ((const int*)rev)[i];
        }
    }
    if (i < NV) {
        g_batch32[i] = is64 ? (int)((const long long*)batch)[i] : ((const int*)batch)[i];
    }
}

// ---------------- weight prep: transpose to [n][k] + bf16 hi/lo split ----------------
__global__ void prep_b_kernel(const float* __restrict__ W1, const float* __restrict__ W2,
                              const float* __restrict__ W3) {
    int i = blockIdx.x * 256 + threadIdx.x;   // [0, 256*832)
    int n, k, K, off; const float* W;
    if (i < 256 * 192)      { n = i / 192; k = i % 192; K = 192; W = W1; off = BOFF_W1; }
    else if (i < 256 * 448) { int j = i - 256 * 192; n = j / 256; k = j % 256; K = 256; W = W2; off = BOFF_W2; }
    else                    { int j = i - 256 * 448; n = j / 384; k = j % 384; K = 384; W = W3; off = BOFF_W3; }
    float v = W[(size_t)k * 256 + n];
    __nv_bfloat16 hi = __float2bfloat16_rn(v);
    __nv_bfloat16 lo = __float2bfloat16_rn(v - __bfloat162float(hi));
    g_bhi[(size_t)off + (size_t)n * K + k] = hi;
    g_blo[(size_t)off + (size_t)n * K + k] = lo;
}

// ---------------- zero kernels ----------------
__global__ void zero_ns_kernel(int which) {
    float4* p = (which == 0) ? (float4*)g_nsA : (float4*)g_nsB;
    size_t i = (size_t)blockIdx.x * blockDim.x + threadIdx.x;
    p[i] = make_float4(0.f, 0.f, 0.f, 0.f);
}
__global__ void zero_buf_kernel(float4* p) {
    size_t i = (size_t)blockIdx.x * blockDim.x + threadIdx.x;
    p[i] = make_float4(0.f, 0.f, 0.f, 0.f);
}

// ---------------- fused bf16x3 mma.sync GEMM ----------------
// Tile M=64 x N=256, BK=32, 256 threads (8 warps, 2x4), warp tile 32x64.
// MODE 0: A=[x[src]|ea]        K=192; epi: h=relu(acc); store h0; red->nsA[dst]
// MODE 1: A=ns[src]-hrev[rev]  K=256; epi: h=relu(h0+acc); opt store; red->ns'[dst]
// MODE 2: A=[x|ns]             K=384; epi: v=relu(acc+b3); red->out[batch]
template <int MODE, bool STOREH>
__global__ void __launch_bounds__(256) mma_gemm(
    const float* __restrict__ x, const float* __restrict__ ea,
    const float* __restrict__ nsrc, const float* __restrict__ hrev,
    const float* __restrict__ hadd, float* hout, float* redtgt,
    const __nv_bfloat16* __restrict__ bhi, const __nv_bfloat16* __restrict__ blo,
    const float* __restrict__ b3)
{
    constexpr int K   = (MODE == 0) ? 192 : (MODE == 1 ? 256 : 384);
    constexpr int NCH = K / 32;

    extern __shared__ char smem[];
    int* sA = (int*)(smem);
    int* sB = (int*)(smem + 256);
    int* sC = (int*)(smem + 512);

    const int tid  = threadIdx.x;
    const int lane = tid & 31;
    const int wid  = tid >> 5;
    const int wm   = wid >> 2;      // 0..1 (M direction)
    const int wn   = wid & 3;       // 0..3 (N direction)
    const int g    = lane >> 2;
    const int tg   = lane & 3;
    const int row0 = blockIdx.x * 64;

    if (tid < 64) {
        if (MODE == 0)      { sA[tid] = g_src32[row0 + tid]; sC[tid] = g_dst32[row0 + tid]; }
        else if (MODE == 1) { sA[tid] = g_src32[row0 + tid]; sB[tid] = g_rev32[row0 + tid];
                              sC[tid] = g_dst32[row0 + tid]; }
        else                { sC[tid] = g_batch32[row0 + tid]; }
    }
    __syncthreads();

    // loader roles
    const int arow = tid >> 2;          // 0..63
    const int ak   = (tid & 3) * 8;     // k offset (8 f32 per thread)
    const int bn   = tid;               // 0..255 (one B row per thread, 32 bf16)

    float4 aR[2];
    float4 bRh[4], bRl[4];

    auto ldg_chunk = [&](int c) {
        const int gk = c * 32 + ak;
        if (MODE == 0) {
            const float* p = (gk < 128) ? &x[(size_t)sA[arow] * 128 + gk]
                                        : &ea[(size_t)(row0 + arow) * 64 + (gk - 128)];
            aR[0] = *(const float4*)p; aR[1] = *(const float4*)(p + 4);
        } else if (MODE == 1) {
            const float* p = &nsrc[(size_t)sA[arow] * 256 + gk];
            const float* q = &hrev[(size_t)sB[arow] * 256 + gk];
            float4 p0 = *(const float4*)p,       p1 = *(const float4*)(p + 4);
            float4 q0 = *(const float4*)q,       q1 = *(const float4*)(q + 4);
            aR[0] = make_float4(p0.x - q0.x, p0.y - q0.y, p0.z - q0.z, p0.w - q0.w);
            aR[1] = make_float4(p1.x - q1.x, p1.y - q1.y, p1.z - q1.z, p1.w - q1.w);
        } else {
            const float* p = (gk < 128) ? &x[(size_t)(row0 + arow) * 128 + gk]
                                        : &nsrc[(size_t)(row0 + arow) * 256 + (gk - 128)];
            aR[0] = *(const float4*)p; aR[1] = *(const float4*)(p + 4);
        }
        const float4* ph = (const float4*)(bhi + (size_t)bn * K + c * 32);
        const float4* pl = (const float4*)(blo + (size_t)bn * K + c * 32);
        #pragma unroll
        for (int j = 0; j < 4; j++) { bRh[j] = ph[j]; bRl[j] = pl[j]; }
    };

    auto sts_chunk = [&](int buf) {
        char* tb = smem + SM_TILES + buf * BUFSZ;
        uint4 H, L;
        split2(aR[0].x, aR[0].y, H.x, L.x);
        split2(aR[0].z, aR[0].w, H.y, L.y);
        split2(aR[1].x, aR[1].y, H.z, L.z);
        split2(aR[1].z, aR[1].w, H.w, L.w);
        *(uint4*)(tb + T_AHI + arow * 80 + ak * 2) = H;
        *(uint4*)(tb + T_ALO + arow * 80 + ak * 2) = L;
        char* pbh = tb + T_BHI + bn * 80;
        char* pbl = tb + T_BLO + bn * 80;
        #pragma unroll
        for (int j = 0; j < 4; j++) {
            *(float4*)(pbh + j * 16) = bRh[j];
            *(float4*)(pbl + j * 16) = bRl[j];
        }
    };

    float acc[2][8][4];
    #pragma unroll
    for (int mt = 0; mt < 2; mt++)
        #pragma unroll
        for (int nt = 0; nt < 8; nt++)
            #pragma unroll
            for (int j = 0; j < 4; j++) acc[mt][nt][j] = 0.f;

    ldg_chunk(0);
    sts_chunk(0);
    __syncthreads();

    #pragma unroll 2
    for (int c = 0; c < NCH; c++) {
        const int buf = c & 1;
        if (c + 1 < NCH) ldg_chunk(c + 1);

        const char* tb = smem + SM_TILES + buf * BUFSZ;
        #pragma unroll
        for (int ks = 0; ks < 2; ks++) {
            const int koff = ks * 32 + tg * 4;
            uint32_t bh[8][2], bl[8][2];
            #pragma unroll
            for (int nt = 0; nt < 8; nt++) {
                const char* pb = tb + (wn * 64 + nt * 8 + g) * 80 + koff;
                bh[nt][0] = *(const uint32_t*)(pb + T_BHI);
                bh[nt][1] = *(const uint32_t*)(pb + T_BHI + 16);
                bl[nt][0] = *(const uint32_t*)(pb + T_BLO);
                bl[nt][1] = *(const uint32_t*)(pb + T_BLO + 16);
            }
            #pragma unroll
            for (int mt = 0; mt < 2; mt++) {
                const char* pa = tb + (wm * 32 + mt * 16 + g) * 80 + koff;
                uint32_t ah[4], al[4];
                ah[0] = *(const uint32_t*)(pa + T_AHI);
                ah[1] = *(const uint32_t*)(pa + T_AHI + 640);
                ah[2] = *(const uint32_t*)(pa + T_AHI + 16);
                ah[3] = *(const uint32_t*)(pa + T_AHI + 640 + 16);
                al[0] = *(const uint32_t*)(pa + T_ALO);
                al[1] = *(const uint32_t*)(pa + T_ALO + 640);
                al[2] = *(const uint32_t*)(pa + T_ALO + 16);
                al[3] = *(const uint32_t*)(pa + T_ALO + 640 + 16);
                #pragma unroll
                for (int nt = 0; nt < 8; nt++) {
                    mma_bf16(acc[mt][nt], ah, bh[nt]);
                    mma_bf16(acc[mt][nt], ah, bl[nt]);
                    mma_bf16(acc[mt][nt], al, bh[nt]);
                }
            }
        }

        if (c + 1 < NCH) {
            __syncthreads();
            sts_chunk((c + 1) & 1);
            __syncthreads();
        }
    }

    // ---- epilogue: stage acc in smem (64 x 264 f32), then coalesced read ----
    __syncthreads();
    float* cs = (float*)(smem + SM_TILES);
    #pragma unroll
    for (int mt = 0; mt < 2; mt++)
        #pragma unroll
        for (int nt = 0; nt < 8; nt++) {
            int row = wm * 32 + mt * 16 + g;
            int col = wn * 64 + nt * 8 + tg * 2;
            *(float2*)&cs[row * 264 + col]       = make_float2(acc[mt][nt][0], acc[mt][nt][1]);
            *(float2*)&cs[(row + 8) * 264 + col] = make_float2(acc[mt][nt][2], acc[mt][nt][3]);
        }
    __syncthreads();

    const int c4 = tid & 63;
    const int rb = tid >> 6;
    float4 bb;
    if (MODE == 2) bb = ((const float4*)b3)[c4];

    #pragma unroll 1
    for (int j = 0; j < 16; j++) {
        const int r = rb * 16 + j;
        float4 v = *(const float4*)&cs[r * 264 + c4 * 4];
        if (MODE == 1) {
            float4 t = *(const float4*)&hadd[(size_t)(row0 + r) * 256 + c4 * 4];
            v = make_float4(v.x + t.x, v.y + t.y, v.z + t.z, v.w + t.w);
        } else if (MODE == 2) {
            v = make_float4(v.x + bb.x, v.y + bb.y, v.z + bb.z, v.w + bb.w);
        }
        v = relu4f(v);
        if (STOREH) *(float4*)&hout[(size_t)(row0 + r) * 256 + c4 * 4] = v;
        red4(&redtgt[(size_t)sC[r] * 256 + c4 * 4], v);
    }
}

// ---------------- launcher ----------------
extern "C" void kernel_launch(void* const* d_in, const int* in_sizes, int n_in,
                              void* d_out, int out_size)
{
    const float *x = nullptr, *ea = nullptr, *W1 = nullptr, *W2 = nullptr, *W3 = nullptr, *b3 = nullptr;
    const void *ei = nullptr, *rev = nullptr, *batch = nullptr;
    for (int i = 0; i < n_in; i++) {
        switch (in_sizes[i]) {
            case 20480000: x     = (const float*)d_in[i]; break;
            case  1280000: ei    = d_in[i];               break;
            case   640000: rev   = d_in[i];               break;
            case 40960000: ea    = (const float*)d_in[i]; break;
            case   160000: batch = d_in[i];               break;
            case    49152: W1    = (const float*)d_in[i]; break;
            case    65536: W2    = (const float*)d_in[i]; break;
            case    98304: W3    = (const float*)d_in[i]; break;
            case      256: b3    = (const float*)d_in[i]; break;
            default: break;
        }
    }
    float* out = (float*)d_out;

    cudaFuncSetAttribute(mma_gemm<0, true >, cudaFuncAttributeMaxDynamicSharedMemorySize, SMEM_TOTAL);
    cudaFuncSetAttribute(mma_gemm<1, true >, cudaFuncAttributeMaxDynamicSharedMemorySize, SMEM_TOTAL);
    cudaFuncSetAttribute(mma_gemm<1, false>, cudaFuncAttributeMaxDynamicSharedMemorySize, SMEM_TOTAL);
    cudaFuncSetAttribute(mma_gemm<2, false>, cudaFuncAttributeMaxDynamicSharedMemorySize, SMEM_TOTAL);

    float* h0p;  cudaGetSymbolAddress((void**)&h0p, g_h0);
    float* hBp;  cudaGetSymbolAddress((void**)&hBp, g_hB);
    float* nsAp; cudaGetSymbolAddress((void**)&nsAp, g_nsA);
    float* nsBp; cudaGetSymbolAddress((void**)&nsBp, g_nsB);
    __nv_bfloat16* bhip; cudaGetSymbolAddress((void**)&bhip, g_bhi);
    __nv_bfloat16* blop; cudaGetSymbolAddress((void**)&blop, g_blo);

    const int NS_ZERO_GRID  = (NV * 256 / 4) / 256;   // 40000
    const int OUT_ZERO_GRID = (NG * 256 / 4) / 256;   // 1250
    const int EGRID = NE / 64;                        // 10000
    const int NGRID = NV / 64;                        // 2500

    detect_kernel<<<1, 32>>>((const unsigned int*)ei);
    convert_kernel<<<NE / 256, 256>>>(ei, rev, batch);
    prep_b_kernel<<<832, 256>>>(W1, W2, W3);
    zero_ns_kernel<<<NS_ZERO_GRID, 256>>>(0);
    zero_ns_kernel<<<NS_ZERO_GRID, 256>>>(1);

    // GEMM0: h0 = relu([x[src]|ea] @ W1); red h0 -> nsA[dst]
    mma_gemm<0, true><<<EGRID, 256, SMEM_TOTAL>>>(
        x, ea, nullptr, nullptr, nullptr, h0p, nsAp, bhip + BOFF_W1, blop + BOFF_W1, nullptr);

    // iter 1: hB = relu(h0 + (nsA[src]-h0[rev]) @ W2); red hB -> nsB[dst]
    mma_gemm<1, true><<<EGRID, 256, SMEM_TOTAL>>>(
        x, ea, nsAp, h0p, h0p, hBp, nsBp, bhip + BOFF_W2, blop + BOFF_W2, nullptr);

    // iter 2: hC = relu(h0 + (nsB[src]-hB[rev]) @ W2); red hC -> nsA[dst] (no store)
    zero_ns_kernel<<<NS_ZERO_GRID, 256>>>(0);
    mma_gemm<1, false><<<EGRID, 256, SMEM_TOTAL>>>(
        x, ea, nsBp, hBp, h0p, nullptr, nsAp, bhip + BOFF_W2, blop + BOFF_W2, nullptr);

    // final: out[batch] += relu([x|nsA] @ W3 + b3)
    zero_buf_kernel<<<OUT_ZERO_GRID, 256>>>((float4*)out);
    mma_gemm<2, false><<<NGRID, 256, SMEM_TOTAL>>>(
        x, ea, nsAp, nullptr, nullptr, nullptr, out, bhip + BOFF_W3, blop + BOFF_W3, b3);
}

// round 5
// speedup vs baseline: 1.6202x; 1.4332x over previous
#include <cuda_runtime.h>
#include <cuda_bf16.h>
#include <cstdint>

#define NE 640000
#define NV 160000
#define NG 5000

// ---------------- device scratch ----------------
__device__ float g_h0[(size_t)NE * 256];
__device__ float g_hB[(size_t)NE * 256];
__device__ float g_nsA[(size_t)NV * 256];
__device__ float g_nsB[(size_t)NV * 256];
__device__ int   g_src32[NE];
__device__ int   g_dst32[NE];
__device__ int   g_rev32[NE];
__device__ int   g_batch32[NV];
__device__ int   g_is64;
// Weights transposed to [n][k] (n=256 rows, k contiguous), bf16 hi/lo split.
#define BOFF_W1 0
#define BOFF_W2 (256 * 192)
#define BOFF_W3 (256 * 448)
__device__ __nv_bfloat16 g_bhi[256 * 832];
__device__ __nv_bfloat16 g_blo[256 * 832];

// ---------------- smem layout ----------------
// [0,512) sA; [512,1024) sB; [1024,1536) sC; stages from 1536.
// Stage: A fp32 128 rows x 160B (= 32 floats + 32B pad) = 20480
//        (MODE1 second A tile at +20480)
//        B bf16 256 rows x 144B (64B hi + 64B lo + 16B pad)= 36864
#define SM_STAGE   1536
#define A_STRIDE   160
#define B_STRIDE   144
#define A_BYTES    20480
#define B_BYTES    36864

// ---------------- helpers ----------------
__device__ __forceinline__ uint32_t smem_u32(const void* p) {
    uint32_t a;
    asm("{ .reg .u64 t; cvta.to.shared.u64 t, %1; cvt.u32.u64 %0, t; }" : "=r"(a) : "l"(p));
    return a;
}
__device__ __forceinline__ void cp16(uint32_t dst, const void* src) {
    asm volatile("cp.async.cg.shared.global [%0], [%1], 16;" :: "r"(dst), "l"(src));
}
__device__ __forceinline__ void cp_commit() {
    asm volatile("cp.async.commit_group;");
}
template <int N>
__device__ __forceinline__ void cp_wait() {
    asm volatile("cp.async.wait_group %0;" :: "n"(N));
}
__device__ __forceinline__ void mma_bf16(float* d, const uint32_t* a, uint32_t b0, uint32_t b1) {
    asm volatile("mma.sync.aligned.m16n8k16.row.col.f32.bf16.bf16.f32 "
        "{%0,%1,%2,%3}, {%4,%5,%6,%7}, {%8,%9}, {%0,%1,%2,%3};"
        : "+f"(d[0]), "+f"(d[1]), "+f"(d[2]), "+f"(d[3])
        : "r"(a[0]), "r"(a[1]), "r"(a[2]), "r"(a[3]), "r"(b0), "r"(b1));
}
__device__ __forceinline__ void split2(float a, float b, uint32_t& hi, uint32_t& lo) {
    __nv_bfloat162 h = __floats2bfloat162_rn(a, b);
    float ra = a - __bfloat162float(h.x);
    float rb = b - __bfloat162float(h.y);
    __nv_bfloat162 l = __floats2bfloat162_rn(ra, rb);
    hi = *reinterpret_cast<uint32_t*>(&h);
    lo = *reinterpret_cast<uint32_t*>(&l);
}
__device__ __forceinline__ void red4(float* p, float4 v) {
    asm volatile("red.global.add.v4.f32 [%0], {%1, %2, %3, %4};"
                 :: "l"(p), "f"(v.x), "f"(v.y), "f"(v.z), "f"(v.w) : "memory");
}
__device__ __forceinline__ float4 relu4f(float4 v) {
    return make_float4(fmaxf(v.x, 0.f), fmaxf(v.y, 0.f), fmaxf(v.z, 0.f), fmaxf(v.w, 0.f));
}

// ---------------- index dtype detection + normalization ----------------
__global__ void detect_kernel(const unsigned int* __restrict__ ei_words) {
    if (threadIdx.x == 0 && blockIdx.x == 0) {
        int allz = 1;
        #pragma unroll 1
        for (int i = 1; i < 128; i += 2) allz &= (ei_words[i] == 0u);
        g_is64 = allz;
    }
}
__global__ void convert_kernel(const void* __restrict__ ei, const void* __restrict__ rev,
                               const void* __restrict__ batch) {
    int i = blockIdx.x * 256 + threadIdx.x;
    const bool is64 = (g_is64 != 0);
    if (i < NE) {
        if (is64) {
            g_src32[i] = (int)((const long long*)ei)[i];
            g_dst32[i] = (int)((const long long*)ei)[NE + i];
            g_rev32[i] = (int)((const long long*)rev)[i];
        } else {
            g_src32[i] = ((const int*)ei)[i];
            g_dst32[i] = ((const int*)ei)[NE + i];
            g_rev32[i] = ((const int*)rev)[i];
        }
    }
    if (i < NV) {
        g_batch32[i] = is64 ? (int)((const long long*)batch)[i] : ((const int*)batch)[i];
    }
}

// ---------------- weight prep ----------------
__global__ void prep_b_kernel(const float* __restrict__ W1, const float* __restrict__ W2,
                              const float* __restrict__ W3) {
    int i = blockIdx.x * 256 + threadIdx.x;
    int n, k, K, off; const float* W;
    if (i < 256 * 192)      { n = i / 192; k = i % 192; K = 192; W = W1; off = BOFF_W1; }
    else if (i < 256 * 448) { int j = i - 256 * 192; n = j / 256; k = j % 256; K = 256; W = W2; off = BOFF_W2; }
    else                    { int j = i - 256 * 448; n = j / 384; k = j % 384; K = 384; W = W3; off = BOFF_W3; }
    float v = W[(size_t)k * 256 + n];
    __nv_bfloat16 hi = __float2bfloat16_rn(v);
    __nv_bfloat16 lo = __float2bfloat16_rn(v - __bfloat162float(hi));
    g_bhi[(size_t)off + (size_t)n * K + k] = hi;
    g_blo[(size_t)off + (size_t)n * K + k] = lo;
}

// ---------------- zero kernels ----------------
__global__ void zero_ns_kernel(int which) {
    float4* p = (which == 0) ? (float4*)g_nsA : (float4*)g_nsB;
    size_t i = (size_t)blockIdx.x * blockDim.x + threadIdx.x;
    p[i] = make_float4(0.f, 0.f, 0.f, 0.f);
}
__global__ void zero_buf_kernel(float4* p) {
    size_t i = (size_t)blockIdx.x * blockDim.x + threadIdx.x;
    p[i] = make_float4(0.f, 0.f, 0.f, 0.f);
}

// ---------------- fused bf16x3 mma.sync GEMM, cp.async pipelined ----------------
// Tile M=128 x N=256, BK=32, 512 threads (16 warps 4x4), warp tile 32x64.
// MODE 0: A=[x[src]|ea]       K=192; epi: h=relu(acc); store h0; red->nsA[dst]
// MODE 1: A=ns[src]-hrev[rev] K=256; epi: h=relu(h0+acc); opt store; red->ns'[dst]
// MODE 2: A=[x|ns]            K=384; epi: v=relu(acc+b3); red->out[batch]
template <int MODE, bool STOREH, int S>
__global__ void __launch_bounds__(512, 1) mma_gemm(
    const float* __restrict__ x, const float* __restrict__ ea,
    const float* __restrict__ nsrc, const float* __restrict__ hrev,
    const float* __restrict__ hadd, float* hout, float* redtgt,
    const __nv_bfloat16* __restrict__ bhi, const __nv_bfloat16* __restrict__ blo,
    const float* __restrict__ b3)
{
    constexpr int K     = (MODE == 0) ? 192 : (MODE == 1 ? 256 : 384);
    constexpr int NCH   = K / 32;
    constexpr int BO    = (MODE == 1) ? 2 * A_BYTES : A_BYTES;    // B offset in stage
    constexpr int STAGE = BO + B_BYTES;

    extern __shared__ char smem[];
    const uint32_t smu = smem_u32(smem);
    int* sA = (int*)(smem);
    int* sB = (int*)(smem + 512);
    int* sC = (int*)(smem + 1024);

    const int tid  = threadIdx.x;
    const int lane = tid & 31;
    const int wid  = tid >> 5;
    const int wm   = wid >> 2;       // 0..3
    const int wn   = wid & 3;        // 0..3
    const int g    = lane >> 2;
    const int tg   = lane & 3;
    const int row0 = blockIdx.x * 128;

    if (tid < 128) {
        if (MODE == 0)      { sA[tid] = g_src32[row0 + tid]; sC[tid] = g_dst32[row0 + tid]; }
        else if (MODE == 1) { sA[tid] = g_src32[row0 + tid]; sB[tid] = g_rev32[row0 + tid];
                              sC[tid] = g_dst32[row0 + tid]; }
        else                { sC[tid] = g_batch32[row0 + tid]; }
    }
    __syncthreads();

    // loader roles: A: thread -> row r, quarter q (8 floats). B: thread -> row n, half (hi/lo).
    const int r = tid >> 2;
    const int q = tid & 3;
    const int bn   = tid >> 1;
    const int bhalf = tid & 1;

    auto issue_chunk = [&](int c, int buf) {
        const uint32_t sb = smu + SM_STAGE + buf * STAGE;
        const int gk = c * 32 + q * 8;
        // ---- A ----
        const float* s;
        if (MODE == 0) {
            s = (gk < 128) ? x + (size_t)sA[r] * 128 + gk
                           : ea + (size_t)(row0 + r) * 64 + (gk - 128);
        } else if (MODE == 1) {
            s = nsrc + (size_t)sA[r] * 256 + gk;
        } else {
            s = (gk < 128) ? x + (size_t)(row0 + r) * 128 + gk
                           : nsrc + (size_t)(row0 + r) * 256 + (gk - 128);
        }
        uint32_t d = sb + r * A_STRIDE + q * 32;
        cp16(d, s); cp16(d + 16, s + 4);
        if (MODE == 1) {
            const float* s2 = hrev + (size_t)sB[r] * 256 + gk;
            uint32_t d2 = d + A_BYTES;
            cp16(d2, s2); cp16(d2 + 16, s2 + 4);
        }
        // ---- B ----
        const __nv_bfloat16* bs = (bhalf ? blo : bhi) + (size_t)bn * K + c * 32;
        uint32_t bd = sb + BO + bn * B_STRIDE + bhalf * 64;
        cp16(bd, bs); cp16(bd + 16, bs + 8); cp16(bd + 32, bs + 16); cp16(bd + 48, bs + 24);
    };

    float acc[2][8][4];
    #pragma unroll
    for (int mt = 0; mt < 2; mt++)
        #pragma unroll
        for (int nt = 0; nt < 8; nt++)
            #pragma unroll
            for (int j = 0; j < 4; j++) acc[mt][nt][j] = 0.f;

    // prologue: issue S-1 stages
    #pragma unroll
    for (int c = 0; c < S - 1; c++) { issue_chunk(c, c); cp_commit(); }

    for (int c = 0; c < NCH; c++) {
        cp_wait<S - 2>();
        __syncthreads();
        // issue next
        if (c + S - 1 < NCH) issue_chunk(c + S - 1, (c + S - 1) % S);
        cp_commit();

        const char* st = smem + SM_STAGE + (c % S) * STAGE;
        #pragma unroll
        for (int ks = 0; ks < 2; ks++) {
            uint32_t ah[2][4], al[2][4];
            #pragma unroll
            for (int mt = 0; mt < 2; mt++) {
                const char* pa = st + (wm * 32 + mt * 16 + g) * A_STRIDE + (ks * 16 + 2 * tg) * 4;
                float2 v0 = *(const float2*)pa;                       // (row, k)
                float2 v1 = *(const float2*)(pa + 8 * A_STRIDE);      // (row+8, k)
                float2 v2 = *(const float2*)(pa + 32);                // (row, k+8)
                float2 v3 = *(const float2*)(pa + 8 * A_STRIDE + 32); // (row+8, k+8)
                if (MODE == 1) {
                    const char* ph = pa + A_BYTES;
                    float2 w0 = *(const float2*)ph;
                    float2 w1 = *(const float2*)(ph + 8 * A_STRIDE);
                    float2 w2 = *(const float2*)(ph + 32);
                    float2 w3 = *(const float2*)(ph + 8 * A_STRIDE + 32);
                    v0.x -= w0.x; v0.y -= w0.y; v1.x -= w1.x; v1.y -= w1.y;
                    v2.x -= w2.x; v2.y -= w2.y; v3.x -= w3.x; v3.y -= w3.y;
                }
                split2(v0.x, v0.y, ah[mt][0], al[mt][0]);
                split2(v1.x, v1.y, ah[mt][1], al[mt][1]);
                split2(v2.x, v2.y, ah[mt][2], al[mt][2]);
                split2(v3.x, v3.y, ah[mt][3], al[mt][3]);
            }
            #pragma unroll
            for (int nt = 0; nt < 8; nt++) {
                const char* pb = st + BO + (wn * 64 + nt * 8 + g) * B_STRIDE + ks * 32 + tg * 4;
                uint32_t bh0 = *(const uint32_t*)pb;
                uint32_t bh1 = *(const uint32_t*)(pb + 16);
                uint32_t bl0 = *(const uint32_t*)(pb + 64);
                uint32_t bl1 = *(const uint32_t*)(pb + 80);
                #pragma unroll
                for (int mt = 0; mt < 2; mt++) {
                    mma_bf16(acc[mt][nt], ah[mt], bh0, bh1);
                    mma_bf16(acc[mt][nt], ah[mt], bl0, bl1);
                    mma_bf16(acc[mt][nt], al[mt], bh0, bh1);
                }
            }
        }
    }

    // ---- epilogue: stage C in smem (128 x 260 f32), coalesced fused writeback ----
    __syncthreads();
    float* cs = (float*)(smem + SM_STAGE);
    #pragma unroll
    for (int mt = 0; mt < 2; mt++)
        #pragma unroll
        for (int nt = 0; nt < 8; nt++) {
            int row = wm * 32 + mt * 16 + g;
            int col = wn * 64 + nt * 8 + tg * 2;
            *(float2*)&cs[row * 260 + col]       = make_float2(acc[mt][nt][0], acc[mt][nt][1]);
            *(float2*)&cs[(row + 8) * 260 + col] = make_float2(acc[mt][nt][2], acc[mt][nt][3]);
        }
    __syncthreads();

    const int c4 = tid & 63;
    const int rb = tid >> 6;
    float4 bb;
    if (MODE == 2) bb = ((const float4*)b3)[c4];

    #pragma unroll 2
    for (int j = 0; j < 16; j++) {
        const int rr = rb * 16 + j;
        float4 v = *(const float4*)&cs[rr * 260 + c4 * 4];
        if (MODE == 1) {
            float4 t = *(const float4*)&hadd[(size_t)(row0 + rr) * 256 + c4 * 4];
            v = make_float4(v.x + t.x, v.y + t.y, v.z + t.z, v.w + t.w);
        } else if (MODE == 2) {
            v = make_float4(v.x + bb.x, v.y + bb.y, v.z + bb.z, v.w + bb.w);
        }
        v = relu4f(v);
        if (STOREH) *(float4*)&hout[(size_t)(row0 + rr) * 256 + c4 * 4] = v;
        red4(&redtgt[(size_t)sC[rr] * 256 + c4 * 4], v);
    }
}

// ---------------- launcher ----------------
extern "C" void kernel_launch(void* const* d_in, const int* in_sizes, int n_in,
                              void* d_out, int out_size)
{
    const float *x = nullptr, *ea = nullptr, *W1 = nullptr, *W2 = nullptr, *W3 = nullptr, *b3 = nullptr;
    const void *ei = nullptr, *rev = nullptr, *batch = nullptr;
    for (int i = 0; i < n_in; i++) {
        switch (in_sizes[i]) {
            case 20480000: x     = (const float*)d_in[i]; break;
            case  1280000: ei    = d_in[i];               break;
            case   640000: rev   = d_in[i];               break;
            case 40960000: ea    = (const float*)d_in[i]; break;
            case   160000: batch = d_in[i];               break;
            case    49152: W1    = (const float*)d_in[i]; break;
            case    65536: W2    = (const float*)d_in[i]; break;
            case    98304: W3    = (const float*)d_in[i]; break;
            case      256: b3    = (const float*)d_in[i]; break;
            default: break;
        }
    }
    float* out = (float*)d_out;

    const int SM02 = SM_STAGE + 3 * (A_BYTES + B_BYTES);          // 173568
    const int SM1  = SM_STAGE + 2 * (2 * A_BYTES + B_BYTES);      // 157184

    cudaFuncSetAttribute(mma_gemm<0, true , 3>, cudaFuncAttributeMaxDynamicSharedMemorySize, SM02);
    cudaFuncSetAttribute(mma_gemm<1, true , 2>, cudaFuncAttributeMaxDynamicSharedMemorySize, SM1);
    cudaFuncSetAttribute(mma_gemm<1, false, 2>, cudaFuncAttributeMaxDynamicSharedMemorySize, SM1);
    cudaFuncSetAttribute(mma_gemm<2, false, 3>, cudaFuncAttributeMaxDynamicSharedMemorySize, SM02);

    float* h0p;  cudaGetSymbolAddress((void**)&h0p, g_h0);
    float* hBp;  cudaGetSymbolAddress((void**)&hBp, g_hB);
    float* nsAp; cudaGetSymbolAddress((void**)&nsAp, g_nsA);
    float* nsBp; cudaGetSymbolAddress((void**)&nsBp, g_nsB);
    __nv_bfloat16* bhip; cudaGetSymbolAddress((void**)&bhip, g_bhi);
    __nv_bfloat16* blop; cudaGetSymbolAddress((void**)&blop, g_blo);

    const int NS_ZERO_GRID  = (NV * 256 / 4) / 256;   // 40000
    const int OUT_ZERO_GRID = (NG * 256 / 4) / 256;   // 1250
    const int EGRID = NE / 128;                       // 5000
    const int NGRID = NV / 128;                       // 1250

    detect_kernel<<<1, 32>>>((const unsigned int*)ei);
    convert_kernel<<<NE / 256, 256>>>(ei, rev, batch);
    prep_b_kernel<<<832, 256>>>(W1, W2, W3);
    zero_ns_kernel<<<NS_ZERO_GRID, 256>>>(0);
    zero_ns_kernel<<<NS_ZERO_GRID, 256>>>(1);

    // GEMM0: h0 = relu([x[src]|ea] @ W1); red h0 -> nsA[dst]
    mma_gemm<0, true, 3><<<EGRID, 512, SM02>>>(
        x, ea, nullptr, nullptr, nullptr, h0p, nsAp, bhip + BOFF_W1, blop + BOFF_W1, nullptr);

    // iter 1: hB = relu(h0 + (nsA[src]-h0[rev]) @ W2); red hB -> nsB[dst]
    mma_gemm<1, true, 2><<<EGRID, 512, SM1>>>(
        x, ea, nsAp, h0p, h0p, hBp, nsBp, bhip + BOFF_W2, blop + BOFF_W2, nullptr);

    // iter 2: hC = relu(h0 + (nsB[src]-hB[rev]) @ W2); red hC -> nsA[dst] (no store)
    zero_ns_kernel<<<NS_ZERO_GRID, 256>>>(0);
    mma_gemm<1, false, 2><<<EGRID, 512, SM1>>>(
        x, ea, nsBp, hBp, h0p, nullptr, nsAp, bhip + BOFF_W2, blop + BOFF_W2, nullptr);

    // final: out[batch] += relu([x|nsA] @ W3 + b3)
    zero_buf_kernel<<<OUT_ZERO_GRID, 256>>>((float4*)out);
    mma_gemm<2, false, 3><<<NGRID, 512, SM02>>>(
        x, ea, nsAp, nullptr, nullptr, nullptr, out, bhip + BOFF_W3, blop + BOFF_W3, b3);
}

// round 6
// speedup vs baseline: 1.6805x; 1.0372x over previous
#include <cuda_runtime.h>
#include <cuda_bf16.h>
#include <cstdint>

#define NE 640000
#define NV 160000
#define NG 5000

// ---------------- device scratch ----------------
__device__ float g_h0[(size_t)NE * 256];
__device__ float g_hB[(size_t)NE * 256];
__device__ float g_nsA[(size_t)NV * 256];
__device__ float g_nsB[(size_t)NV * 256];
__device__ int   g_src32[NE];
__device__ int   g_dst32[NE];
__device__ int   g_rev32[NE];
__device__ int   g_batch32[NV];
__device__ int   g_is64;
// Weights packed chunk-major + SW128-swizzled, bf16 hi/lo per 32-k chunk (32KB/chunk).
// W1: chunks 0..5, W2: 6..13, W3: 14..25.
__device__ __align__(1024) char g_bpk[26 * 32768];

// ---------------- helpers ----------------
__device__ __forceinline__ uint32_t smem_u32(const void* p) {
    uint32_t a;
    asm("{ .reg .u64 t; cvta.to.shared.u64 t, %1; cvt.u32.u64 %0, t; }" : "=r"(a) : "l"(p));
    return a;
}
__device__ __forceinline__ void mbar_init(uint32_t addr, uint32_t cnt) {
    asm volatile("mbarrier.init.shared.b64 [%0], %1;" :: "r"(addr), "r"(cnt) : "memory");
}
__device__ __forceinline__ void mbar_expect(uint32_t addr, uint32_t bytes) {
    asm volatile("mbarrier.arrive.expect_tx.shared.b64 _, [%0], %1;"
                 :: "r"(addr), "r"(bytes) : "memory");
}
__device__ __forceinline__ void mbar_wait(uint32_t addr, uint32_t par) {
    asm volatile("{\n\t.reg .pred P;\n"
        "W%=:\n\t"
        "mbarrier.try_wait.parity.acquire.cta.shared::cta.b64 P, [%0], %1, 0x989680;\n\t"
        "@!P bra W%=;\n\t}\n" :: "r"(addr), "r"(par) : "memory");
}
__device__ __forceinline__ void bulk_g2s(uint32_t dst, const void* src, uint32_t bytes, uint32_t mbar) {
    asm volatile("cp.async.bulk.shared::cta.global.mbarrier::complete_tx::bytes [%0], [%1], %2, [%3];"
                 :: "r"(dst), "l"(src), "r"(bytes), "r"(mbar) : "memory");
}
__device__ __forceinline__ void fence_async() {
    asm volatile("fence.proxy.async.shared::cta;" ::: "memory");
}
__device__ __forceinline__ void mma_bf16(float* d, const uint32_t* a, uint32_t b0, uint32_t b1) {
    asm volatile("mma.sync.aligned.m16n8k16.row.col.f32.bf16.bf16.f32 "
        "{%0,%1,%2,%3}, {%4,%5,%6,%7}, {%8,%9}, {%0,%1,%2,%3};"
        : "+f"(d[0]), "+f"(d[1]), "+f"(d[2]), "+f"(d[3])
        : "r"(a[0]), "r"(a[1]), "r"(a[2]), "r"(a[3]), "r"(b0), "r"(b1));
}
__device__ __forceinline__ void split2(float a, float b, uint32_t& hi, uint32_t& lo) {
    __nv_bfloat162 h = __floats2bfloat162_rn(a, b);
    float ra = a - __bfloat162float(h.x);
    float rb = b - __bfloat162float(h.y);
    __nv_bfloat162 l = __floats2bfloat162_rn(ra, rb);
    hi = *reinterpret_cast<uint32_t*>(&h);
    lo = *reinterpret_cast<uint32_t*>(&l);
}
__device__ __forceinline__ void red4(float* p, float4 v) {
    asm volatile("red.global.add.v4.f32 [%0], {%1, %2, %3, %4};"
                 :: "l"(p), "f"(v.x), "f"(v.y), "f"(v.z), "f"(v.w) : "memory");
}
__device__ __forceinline__ float4 relu4f(float4 v) {
    return make_float4(fmaxf(v.x, 0.f), fmaxf(v.y, 0.f), fmaxf(v.z, 0.f), fmaxf(v.w, 0.f));
}

// ---------------- index dtype detection + normalization ----------------
__global__ void detect_kernel(const unsigned int* __restrict__ ei_words) {
    if (threadIdx.x == 0 && blockIdx.x == 0) {
        int allz = 1;
        #pragma unroll 1
        for (int i = 1; i < 128; i += 2) allz &= (ei_words[i] == 0u);
        g_is64 = allz;
    }
}
__global__ void convert_kernel(const void* __restrict__ ei, const void* __restrict__ rev,
                               const void* __restrict__ batch) {
    int i = blockIdx.x * 256 + threadIdx.x;
    const bool is64 = (g_is64 != 0);
    if (i < NE) {
        if (is64) {
            g_src32[i] = (int)((const long long*)ei)[i];
            g_dst32[i] = (int)((const long long*)ei)[NE + i];
            g_rev32[i] = (int)((const long long*)rev)[i];
        } else {
            g_src32[i] = ((const int*)ei)[i];
            g_dst32[i] = ((const int*)ei)[NE + i];
            g_rev32[i] = ((const int*)rev)[i];
        }
    }
    if (i < NV) {
        g_batch32[i] = is64 ? (int)((const long long*)batch)[i] : ((const int*)batch)[i];
    }
}

// ---------------- weight prep: chunk-major, SW128-swizzled, bf16 hi/lo ----------------
// Chunk = 32 k-values. Row n = 128B: segs 0-3 = hi (k0..31), segs 4-7 = lo.
// Element (n,k,sel) at: n*128 + ((sel*4 + k/8) ^ (n&7))*16 + (k%8)*2.
__global__ void prep_b_kernel(const float* __restrict__ W1, const float* __restrict__ W2,
                              const float* __restrict__ W3) {
    int i = blockIdx.x * 256 + threadIdx.x;   // 26*8192 = 212992 total
    int cg  = i >> 13;
    int rem = i & 8191;
    int n = rem >> 5;
    int k = rem & 31;
    const float* W; int c;
    if (cg < 6)       { W = W1; c = cg; }
    else if (cg < 14) { W = W2; c = cg - 6; }
    else              { W = W3; c = cg - 14; }
    int gk = c * 32 + k;
    float v = W[(size_t)gk * 256 + n];
    __nv_bfloat16 hi = __float2bfloat16_rn(v);
    __nv_bfloat16 lo = __float2bfloat16_rn(v - __bfloat162float(hi));
    char* base = g_bpk + (size_t)cg * 32768 + n * 128;
    int xr = n & 7;
    *(__nv_bfloat16*)(base + (((k >> 3)     ^ xr) * 16) + (k & 7) * 2) = hi;
    *(__nv_bfloat16*)(base + ((((k >> 3) + 4) ^ xr) * 16) + (k & 7) * 2) = lo;
}

// ---------------- zero kernels ----------------
__global__ void zero_ns_kernel(int which) {
    float4* p = (which == 0) ? (float4*)g_nsA : (float4*)g_nsB;
    size_t i = (size_t)blockIdx.x * blockDim.x + threadIdx.x;
    p[i] = make_float4(0.f, 0.f, 0.f, 0.f);
}
__global__ void zero_buf_kernel(float4* p) {
    size_t i = (size_t)blockIdx.x * blockDim.x + threadIdx.x;
    p[i] = make_float4(0.f, 0.f, 0.f, 0.f);
}

// ---------------- fused bf16x3 mma.sync GEMM, cp.async.bulk fed ----------------
// Tile M=64 x N=256, 256 threads (8 warps 2x4), warp tile 32x64.
// A resident per CTA (bulk per row, padded strides); B ring of 32KB chunk bulks.
// MODE 0: A=[x[src]|ea]       K=192; epi: h=relu(acc); store h0; red->nsA[dst]
// MODE 1: A=ns[src]-hrev[rev] K=256; epi: h=relu(h0+acc); opt store; red->ns'[dst]
// MODE 2: A=[x|ns]            K=384; epi: v=relu(acc+b3); red->out[batch]
template <int MODE, bool STOREH>
__global__ void __launch_bounds__(256, 1) mma_gemm(
    const float* __restrict__ x, const float* __restrict__ ea,
    const float* __restrict__ nsrc, const float* __restrict__ hrev,
    const float* __restrict__ hadd, float* hout, float* redtgt,
    const char* __restrict__ bpk, const float* __restrict__ b3)
{
    constexpr int K      = (MODE == 0) ? 192 : (MODE == 1 ? 256 : 384);
    constexpr int NCH    = K / 32;
    constexpr int S      = (MODE == 1) ? 2 : 3;
    constexpr int A0S    = (MODE == 1) ? 1040 : 528;              // tile0 row stride
    constexpr int A1OFF  = (MODE == 1) ? 66560 : 33792;           // tile1 offset
    constexpr int A1S    = (MODE == 0) ? 272 : 1040;              // tile1 row stride
    constexpr int BOFF   = (MODE == 0) ? 51200 : (MODE == 1 ? 133120 : 100352);
    constexpr int ABYTES = (MODE == 0) ? 49152 : (MODE == 1 ? 131072 : 98304);
    constexpr int IDXOFF = BOFF + S * 32768;
    constexpr int BAROFF = IDXOFF + 256;

    extern __shared__ char smem[];
    const uint32_t smu = smem_u32(smem);
    const uint32_t bA  = smu + BAROFF;
    const uint32_t bB  = smu + BAROFF + 8;
    int* sC = (int*)(smem + IDXOFF);

    const int tid  = threadIdx.x;
    const int lane = tid & 31;
    const int wid  = tid >> 5;
    const int wm   = wid >> 2;       // 0..1
    const int wn   = wid & 3;        // 0..3
    const int g    = lane >> 2;
    const int tg   = lane & 3;
    const int row0 = blockIdx.x * 64;

    if (tid < 64) {
        sC[tid] = (MODE == 2) ? g_batch32[row0 + tid] : g_dst32[row0 + tid];
    }
    if (tid == 0) {
        mbar_init(bA, 1);
        #pragma unroll
        for (int s = 0; s < S; s++) mbar_init(bB + s * 8, 1);
    }
    __syncthreads();
    if (tid == 0) {
        fence_async();
        mbar_expect(bA, ABYTES);
    }
    __syncthreads();

    // ---- A bulks: one per row ----
    if (tid < 64) {
        if (MODE == 0)
            bulk_g2s(smu + tid * A0S, x + (size_t)g_src32[row0 + tid] * 128, 512, bA);
        else if (MODE == 1)
            bulk_g2s(smu + tid * A0S, nsrc + (size_t)g_src32[row0 + tid] * 256, 1024, bA);
        else
            bulk_g2s(smu + tid * A0S, x + (size_t)(row0 + tid) * 128, 512, bA);
    } else if (tid < 128) {
        const int r = tid - 64;
        if (MODE == 0)
            bulk_g2s(smu + A1OFF + r * A1S, ea + (size_t)(row0 + r) * 64, 256, bA);
        else if (MODE == 1)
            bulk_g2s(smu + A1OFF + r * A1S, hrev + (size_t)g_rev32[row0 + r] * 256, 1024, bA);
        else
            bulk_g2s(smu + A1OFF + r * A1S, nsrc + (size_t)(row0 + r) * 256, 1024, bA);
    }
    // ---- B prologue: S chunks ----
    if (tid == 0) {
        #pragma unroll
        for (int s = 0; s < S && s < NCH; s++) {
            mbar_expect(bB + s * 8, 32768);
            bulk_g2s(smu + BOFF + s * 32768, bpk + (size_t)s * 32768, 32768, bB + s * 8);
        }
    }

    float acc[2][8][4];
    #pragma unroll
    for (int mt = 0; mt < 2; mt++)
        #pragma unroll
        for (int nt = 0; nt < 8; nt++)
            #pragma unroll
            for (int j = 0; j < 4; j++) acc[mt][nt][j] = 0.f;

    mbar_wait(bA, 0);

    #pragma unroll 1
    for (int c = 0; c < NCH; c++) {
        mbar_wait(bB + (c % S) * 8, (c / S) & 1);

        const char* st = smem + BOFF + (c % S) * 32768;
        #pragma unroll
        for (int ks = 0; ks < 2; ks++) {
            // ---- A fragments ----
            uint32_t ah[2][4], al[2][4];
            const int kk = c * 32 + ks * 16 + 2 * tg;
            #pragma unroll
            for (int mt = 0; mt < 2; mt++) {
                const int row = wm * 32 + mt * 16 + g;
                const char* pa;
                int stride;
                if (MODE == 1) { pa = smem + row * A0S + kk * 4; stride = A0S; }
                else if (kk < 128) { pa = smem + row * A0S + kk * 4; stride = A0S; }
                else { pa = smem + A1OFF + row * A1S + (kk - 128) * 4; stride = A1S; }
                float2 v0 = *(const float2*)pa;
                float2 v1 = *(const float2*)(pa + 8 * stride);
                float2 v2 = *(const float2*)(pa + 32);
                float2 v3 = *(const float2*)(pa + 8 * stride + 32);
                if (MODE == 1) {
                    const char* ph = smem + A1OFF + row * A1S + kk * 4;
                    float2 w0 = *(const float2*)ph;
                    float2 w1 = *(const float2*)(ph + 8 * A1S);
                    float2 w2 = *(const float2*)(ph + 32);
                    float2 w3 = *(const float2*)(ph + 8 * A1S + 32);
                    v0.x -= w0.x; v0.y -= w0.y; v1.x -= w1.x; v1.y -= w1.y;
                    v2.x -= w2.x; v2.y -= w2.y; v3.x -= w3.x; v3.y -= w3.y;
                }
                split2(v0.x, v0.y, ah[mt][0], al[mt][0]);
                split2(v1.x, v1.y, ah[mt][1], al[mt][1]);
                split2(v2.x, v2.y, ah[mt][2], al[mt][2]);
                split2(v3.x, v3.y, ah[mt][3], al[mt][3]);
            }
            // ---- B fragments (swizzled, conflict-free LDS.32) ----
            const int oh0 = (((ks * 2)     ) ^ g) * 16 + tg * 4;
            const int oh1 = (((ks * 2) + 1 ) ^ g) * 16 + tg * 4;
            const int ol0 = (((ks * 2) + 4 ) ^ g) * 16 + tg * 4;
            const int ol1 = (((ks * 2) + 5 ) ^ g) * 16 + tg * 4;
            const char* pb0 = st + (wn * 64 + g) * 128;
            #pragma unroll
            for (int nt = 0; nt < 8; nt++) {
                const char* pb = pb0 + nt * 1024;
                uint32_t bh0 = *(const uint32_t*)(pb + oh0);
                uint32_t bh1 = *(const uint32_t*)(pb + oh1);
                uint32_t bl0 = *(const uint32_t*)(pb + ol0);
                uint32_t bl1 = *(const uint32_t*)(pb + ol1);
                #pragma unroll
                for (int mt = 0; mt < 2; mt++) {
                    mma_bf16(acc[mt][nt], ah[mt], bh0, bh1);
                    mma_bf16(acc[mt][nt], ah[mt], bl0, bl1);
                    mma_bf16(acc[mt][nt], al[mt], bh0, bh1);
                }
            }
        }

        __syncthreads();   // all warps done with stage c%S
        if (tid == 0 && c + S < NCH) {
            fence_async();
            mbar_expect(bB + (c % S) * 8, 32768);
            bulk_g2s(smu + BOFF + (c % S) * 32768, bpk + (size_t)(c + S) * 32768,
                     32768, bB + (c % S) * 8);
        }
    }

    // ---- epilogue: stage C (64 x 260 f32) at smem offset 0, then fused writeback ----
    float* cs = (float*)smem;
    #pragma unroll
    for (int mt = 0; mt < 2; mt++)
        #pragma unroll
        for (int nt = 0; nt < 8; nt++) {
            int row = wm * 32 + mt * 16 + g;
            int col = wn * 64 + nt * 8 + tg * 2;
            *(float2*)&cs[row * 260 + col]       = make_float2(acc[mt][nt][0], acc[mt][nt][1]);
            *(float2*)&cs[(row + 8) * 260 + col] = make_float2(acc[mt][nt][2], acc[mt][nt][3]);
        }
    __syncthreads();

    const int c4 = tid & 63;
    const int rb = tid >> 6;
    float4 bb;
    if (MODE == 2) bb = ((const float4*)b3)[c4];

    #pragma unroll 2
    for (int j = 0; j < 16; j++) {
        const int rr = rb * 16 + j;
        float4 v = *(const float4*)&cs[rr * 260 + c4 * 4];
        if (MODE == 1) {
            float4 t = *(const float4*)&hadd[(size_t)(row0 + rr) * 256 + c4 * 4];
            v = make_float4(v.x + t.x, v.y + t.y, v.z + t.z, v.w + t.w);
        } else if (MODE == 2) {
            v = make_float4(v.x + bb.x, v.y + bb.y, v.z + bb.z, v.w + bb.w);
        }
        v = relu4f(v);
        if (STOREH) *(float4*)&hout[(size_t)(row0 + rr) * 256 + c4 * 4] = v;
        red4(&redtgt[(size_t)sC[rr] * 256 + c4 * 4], v);
    }
}

// ---------------- launcher ----------------
extern "C" void kernel_launch(void* const* d_in, const int* in_sizes, int n_in,
                              void* d_out, int out_size)
{
    const float *x = nullptr, *ea = nullptr, *W1 = nullptr, *W2 = nullptr, *W3 = nullptr, *b3 = nullptr;
    const void *ei = nullptr, *rev = nullptr, *batch = nullptr;
    for (int i = 0; i < n_in; i++) {
        switch (in_sizes[i]) {
            case 20480000: x     = (const float*)d_in[i]; break;
            case  1280000: ei    = d_in[i];               break;
            case   640000: rev   = d_in[i];               break;
            case 40960000: ea    = (const float*)d_in[i]; break;
            case   160000: batch = d_in[i];               break;
            case    49152: W1    = (const float*)d_in[i]; break;
            case    65536: W2    = (const float*)d_in[i]; break;
            case    98304: W3    = (const float*)d_in[i]; break;
            case      256: b3    = (const float*)d_in[i]; break;
            default: break;
        }
    }
    float* out = (float*)d_out;

    const int SM0 = 149824;   // 51200 + 3*32768 + 320
    const int SM1 = 198976;   // 133120 + 2*32768 + 320
    const int SM2 = 198976;   // 100352 + 3*32768 + 320

    cudaFuncSetAttribute(mma_gemm<0, true >, cudaFuncAttributeMaxDynamicSharedMemorySize, SM0);
    cudaFuncSetAttribute(mma_gemm<1, true >, cudaFuncAttributeMaxDynamicSharedMemorySize, SM1);
    cudaFuncSetAttribute(mma_gemm<1, false>, cudaFuncAttributeMaxDynamicSharedMemorySize, SM1);
    cudaFuncSetAttribute(mma_gemm<2, false>, cudaFuncAttributeMaxDynamicSharedMemorySize, SM2);

    float* h0p;  cudaGetSymbolAddress((void**)&h0p, g_h0);
    float* hBp;  cudaGetSymbolAddress((void**)&hBp, g_hB);
    float* nsAp; cudaGetSymbolAddress((void**)&nsAp, g_nsA);
    float* nsBp; cudaGetSymbolAddress((void**)&nsBp, g_nsB);
    char*  bpkp; cudaGetSymbolAddress((void**)&bpkp, g_bpk);

    const char* bW1 = bpkp;
    const char* bW2 = bpkp + 6 * 32768;
    const char* bW3 = bpkp + 14 * 32768;

    const int NS_ZERO_GRID  = (NV * 256 / 4) / 256;   // 40000
    const int OUT_ZERO_GRID = (NG * 256 / 4) / 256;   // 1250
    const int EGRID = NE / 64;                        // 10000
    const int NGRID = NV / 64;                        // 2500

    detect_kernel<<<1, 32>>>((const unsigned int*)ei);
    convert_kernel<<<NE / 256, 256>>>(ei, rev, batch);
    prep_b_kernel<<<832, 256>>>(W1, W2, W3);
    zero_ns_kernel<<<NS_ZERO_GRID, 256>>>(0);
    zero_ns_kernel<<<NS_ZERO_GRID, 256>>>(1);

    // GEMM0: h0 = relu([x[src]|ea] @ W1); red h0 -> nsA[dst]
    mma_gemm<0, true><<<EGRID, 256, SM0>>>(
        x, ea, nullptr, nullptr, nullptr, h0p, nsAp, bW1, nullptr);

    // iter 1: hB = relu(h0 + (nsA[src]-h0[rev]) @ W2); red hB -> nsB[dst]
    mma_gemm<1, true><<<EGRID, 256, SM1>>>(
        x, ea, nsAp, h0p, h0p, hBp, nsBp, bW2, nullptr);

    // iter 2: hC = relu(h0 + (nsB[src]-hB[rev]) @ W2); red hC -> nsA[dst] (no store)
    zero_ns_kernel<<<NS_ZERO_GRID, 256>>>(0);
    mma_gemm<1, false><<<EGRID, 256, SM1>>>(
        x, ea, nsBp, hBp, h0p, nullptr, nsAp, bW2, nullptr);

    // final: out[batch] += relu([x|nsA] @ W3 + b3)
    zero_buf_kernel<<<OUT_ZERO_GRID, 256>>>((float4*)out);
    mma_gemm<2, false><<<NGRID, 256, SM2>>>(
        x, ea, nsAp, nullptr, nullptr, nullptr, out, bW3, b3);
}